// round 1
// baseline (speedup 1.0000x reference)
#include <cuda_runtime.h>
#include <math.h>

// ---------------------------------------------------------------------------
// BboxLoss (CIoU + DFL) for B=32, A=8400, RM=16, NC=80.
// Strategy: warp-per-anchor, skip non-foreground anchors entirely (only ~10%
// of anchors are fg, and ALL heavy arrays are only needed where fg is set).
// Last-block finalize -> only 2 kernel launches in the graph.
// ---------------------------------------------------------------------------

#define WARPS_PER_BLOCK 8
#define THREADS_PER_BLOCK (WARPS_PER_BLOCK * 32)
#define GRID_BLOCKS 2960

#define EPSF 1e-7f
#define FOUR_OVER_PI2 0.40528473456935108577f   // 4 / pi^2
#define RM 16
#define NC 80

__device__ double       g_acc[3];   // [0]=sum (1-ciou)*w, [1]=sum dfl, [2]=num_fg
__device__ unsigned int g_done;
__device__ int          g_mode;     // 0 = int32 mask, 1 = float32 mask, 2 = bool/byte mask

// ---------------------------------------------------------------------------
// Kernel 1: zero accumulators + detect fg_mask storage dtype.
// Scans only min-footprint (BA bytes = BA/4 words) so it is in-bounds for
// every candidate dtype. Bool is the safe fallback (smallest footprint; an
// all-zero buffer gives identical results under any interpretation).
// ---------------------------------------------------------------------------
__global__ void init_detect_kernel(const unsigned int* __restrict__ mw, int nwords)
{
    __shared__ int s_not_int, s_not_float, s_any;
    int tid = threadIdx.x;
    if (tid == 0) {
        g_acc[0] = 0.0; g_acc[1] = 0.0; g_acc[2] = 0.0;
        g_done = 0u;
        s_not_int = 0; s_not_float = 0; s_any = 0;
    }
    __syncthreads();

    int ni = 0, nf = 0, any = 0;
    for (int i = tid; i < nwords; i += blockDim.x) {
        unsigned int v = mw[i];
        if (v != 0u) any = 1;
        if (v > 1u)  ni = 1;
        float f = __uint_as_float(v);
        if (!(f == 0.0f || f == 1.0f)) nf = 1;
    }
    if (ni)  s_not_int = 1;
    if (nf)  s_not_float = 1;
    if (any) s_any = 1;
    __syncthreads();

    if (tid == 0) {
        int mode;
        if (!s_any)            mode = 2;  // all zero -> bool interpretation is safe
        else if (!s_not_int)   mode = 0;  // every word in {0,1} -> int32
        else if (!s_not_float) mode = 1;  // every word in {0.0f,1.0f} -> float32
        else                   mode = 2;  // packed bytes -> bool
        g_mode = mode;
    }
}

// ---------------------------------------------------------------------------
// Kernel 2: main loss. One warp per anchor (grid-stride).
// ---------------------------------------------------------------------------
__global__ __launch_bounds__(THREADS_PER_BLOCK)
void bbox_loss_kernel(const float* __restrict__ pred_dist,
                      const float* __restrict__ pred_bboxes,
                      const float* __restrict__ anchor_points,
                      const float* __restrict__ target_bboxes,
                      const float* __restrict__ target_scores,
                      const float* __restrict__ tss,
                      const void*  __restrict__ fg_mask,
                      float*       __restrict__ out,
                      int BA, int A, int out_size)
{
    const int lane = threadIdx.x & 31;
    const int wid  = threadIdx.x >> 5;
    const int gw   = blockIdx.x * WARPS_PER_BLOCK + wid;
    const int nw   = gridDim.x * WARPS_PER_BLOCK;
    const int mode = g_mode;

    double acc_iou = 0.0, acc_dfl = 0.0, acc_fg = 0.0;

    for (int n = gw; n < BA; n += nw) {
        bool fg;
        if (mode == 2)      fg = ((const unsigned char*)fg_mask)[n] != 0;
        else if (mode == 0) fg = ((const int*)fg_mask)[n] != 0;
        else                fg = ((const float*)fg_mask)[n] != 0.0f;
        if (!fg) continue;

        const int a = n % A;

        // ---- weight = target_scores[n].sum() : 80 floats = 20 float4 ----
        float wsum = 0.0f;
        {
            const float4* tv = (const float4*)(target_scores + (size_t)n * NC);
            if (lane < NC / 4) {
                float4 q = tv[lane];
                wsum = (q.x + q.y) + (q.z + q.w);
            }
            #pragma unroll
            for (int o = 16; o; o >>= 1)
                wsum += __shfl_xor_sync(0xffffffffu, wsum, o);
        }

        // ---- boxes + anchor (broadcast loads) ----
        float4 bp  = ((const float4*)pred_bboxes)[n];
        float4 bt  = ((const float4*)target_bboxes)[n];
        float2 apt = ((const float2*)anchor_points)[a];

        // ---- DFL: lanes 0..15 read pred_dist (64 floats); 4-lane group = one side ----
        float x0 = 0.f, x1 = 0.f, x2 = 0.f, x3 = 0.f;
        if (lane < 16) {
            float4 q = ((const float4*)(pred_dist + (size_t)n * (4 * RM)))[lane];
            x0 = q.x; x1 = q.y; x2 = q.z; x3 = q.w;
        }
        float m = fmaxf(fmaxf(x0, x1), fmaxf(x2, x3));
        m = fmaxf(m, __shfl_xor_sync(0xffffffffu, m, 1, 4));
        m = fmaxf(m, __shfl_xor_sync(0xffffffffu, m, 2, 4));
        float se = expf(x0 - m) + expf(x1 - m) + expf(x2 - m) + expf(x3 - m);
        se += __shfl_xor_sync(0xffffffffu, se, 1, 4);
        se += __shfl_xor_sync(0xffffffffu, se, 2, 4);
        float logZ = m + logf(se);

        // target ltrb distance for this side, clipped to [0, RM-1-0.01]
        float tv0 = apt.x - bt.x, tv1 = apt.y - bt.y;
        float tv2 = bt.z - apt.x, tv3 = bt.w - apt.y;
        int   s = (lane >> 2) & 3;
        float t = (s == 0) ? tv0 : (s == 1) ? tv1 : (s == 2) ? tv2 : tv3;
        t = fminf(fmaxf(t, 0.0f), (float)(RM - 1) - 0.01f);
        int   tl = (int)t;
        int   tr = min(tl + 1, RM - 1);
        float wl = (float)(tl + 1) - t;
        float wr = 1.0f - wl;

        // select x[tl], x[tr] within the 4-lane group (each lane owns 4 bins)
        int base = (lane & 3) * 4;
        int dl = tl - base, dr = tr - base;
        float xl = 0.f, xr = 0.f;
        if (dl >= 0 && dl < 4) xl = (dl == 0) ? x0 : (dl == 1) ? x1 : (dl == 2) ? x2 : x3;
        if (dr >= 0 && dr < 4) xr = (dr == 0) ? x0 : (dr == 1) ? x1 : (dr == 2) ? x2 : x3;
        xl += __shfl_xor_sync(0xffffffffu, xl, 1, 4);
        xl += __shfl_xor_sync(0xffffffffu, xl, 2, 4);
        xr += __shfl_xor_sync(0xffffffffu, xr, 1, 4);
        xr += __shfl_xor_sync(0xffffffffu, xr, 2, 4);

        // dfl_side = -(x_tl - logZ)*wl - (x_tr - logZ)*wr = logZ - (x_tl*wl + x_tr*wr)
        float dfl_side = logZ - (xl * wl + xr * wr);
        float dc = (lane < 16 && (lane & 3) == 0) ? dfl_side : 0.f;
        #pragma unroll
        for (int o = 16; o; o >>= 1)
            dc += __shfl_xor_sync(0xffffffffu, dc, o);

        // ---- CIoU on lane 0 ----
        if (lane == 0) {
            float x11 = bp.x, y11 = bp.y, x21 = bp.z, y21 = bp.w;
            float x12 = bt.x, y12 = bt.y, x22 = bt.z, y22 = bt.w;
            float iw = fmaxf(fminf(x21, x22) - fmaxf(x11, x12), 0.f);
            float ih = fmaxf(fminf(y21, y22) - fmaxf(y11, y12), 0.f);
            float inter = iw * ih;
            float w1 = x21 - x11, h1 = y21 - y11;
            float w2 = x22 - x12, h2 = y22 - y12;
            float uni = w1 * h1 + w2 * h2 - inter + EPSF;
            float iou = inter / uni;
            float cw = fmaxf(x21, x22) - fminf(x11, x12);
            float ch = fmaxf(y21, y22) - fminf(y11, y12);
            float c2 = cw * cw + ch * ch + EPSF;
            float dx = x11 + x21 - x12 - x22;
            float dy = y11 + y21 - y12 - y22;
            float rho2 = (dx * dx + dy * dy) * 0.25f;
            float dat = atanf(w1 / (h1 + EPSF)) - atanf(w2 / (h2 + EPSF));
            float v = FOUR_OVER_PI2 * dat * dat;
            float alpha = v / (1.0f - iou + v + EPSF);
            float ciou = iou - (rho2 / c2 + v * alpha);

            acc_iou += (double)((1.0f - ciou) * wsum);
            acc_dfl += (double)dc;
            acc_fg  += 1.0;
        }
    }

    // ---- block reduction ----
    __shared__ double s0[WARPS_PER_BLOCK], s1[WARPS_PER_BLOCK], s2[WARPS_PER_BLOCK];
    if (lane == 0) { s0[wid] = acc_iou; s1[wid] = acc_dfl; s2[wid] = acc_fg; }
    __syncthreads();

    if (threadIdx.x == 0) {
        double a0 = 0, a1 = 0, a2 = 0;
        #pragma unroll
        for (int i = 0; i < WARPS_PER_BLOCK; i++) { a0 += s0[i]; a1 += s1[i]; a2 += s2[i]; }
        atomicAdd(&g_acc[0], a0);
        atomicAdd(&g_acc[1], a1);
        atomicAdd(&g_acc[2], a2);
        __threadfence();
        unsigned int prev = atomicAdd(&g_done, 1u);
        if (prev == gridDim.x - 1) {
            double si  = *((volatile double*)&g_acc[0]);
            double sd  = *((volatile double*)&g_acc[1]);
            double nfg = *((volatile double*)&g_acc[2]);
            double li = si / (double)tss[0];
            double ld = sd / fmax(nfg * 4.0, 1.0);
            if (out_size >= 1) out[0] = (float)li;
            if (out_size >= 2) out[1] = (float)ld;
        }
    }
}

// ---------------------------------------------------------------------------
// Launch. Inputs (metadata order): pred_dist, pred_bboxes, anchor_points,
// target_bboxes, target_scores, target_scores_sum, fg_mask.
// ---------------------------------------------------------------------------
extern "C" void kernel_launch(void* const* d_in, const int* in_sizes, int n_in,
                              void* d_out, int out_size)
{
    const float* pred_dist     = (const float*)d_in[0];
    const float* pred_bboxes   = (const float*)d_in[1];
    const float* anchor_points = (const float*)d_in[2];
    const float* target_bboxes = (const float*)d_in[3];
    const float* target_scores = (const float*)d_in[4];
    const float* tss           = (const float*)d_in[5];
    const void*  fg_mask       = (const void*)d_in[6];

    const int BA = in_sizes[6];        // B*A anchors (element count of fg_mask)
    const int A  = in_sizes[2] / 2;    // anchor_points is (A,2)

    init_detect_kernel<<<1, 1024>>>((const unsigned int*)fg_mask, BA >> 2);

    int warps_needed = BA;  // one anchor per warp minimum work unit
    int blocks = (warps_needed + WARPS_PER_BLOCK - 1) / WARPS_PER_BLOCK;
    if (blocks > GRID_BLOCKS) blocks = GRID_BLOCKS;

    bbox_loss_kernel<<<blocks, THREADS_PER_BLOCK>>>(
        pred_dist, pred_bboxes, anchor_points, target_bboxes, target_scores,
        tss, fg_mask, (float*)d_out, BA, A, out_size);
}

// round 2
// speedup vs baseline: 1.6280x; 1.6280x over previous
#include <cuda_runtime.h>
#include <math.h>

// ---------------------------------------------------------------------------
// BboxLoss (CIoU + DFL), B=32, A=8400, RM=16, NC=80.
// R2: stream compaction. 4 launches:
//   1) init:   zero flags/accumulators
//   2) detect: classify fg_mask storage dtype (bool bytes / int32 / float32)
//   3) compact: warp-aggregated append of fg anchor indices -> dense list
//   4) process: warp-per-fg-anchor over the dense list, last-block finalize
// ---------------------------------------------------------------------------

#define EPSF 1e-7f
#define FOUR_OVER_PI2 0.40528473456935108577f   // 4 / pi^2
#define RM 16
#define NC 80

#define CB_THREADS 256
#define PB_WARPS   8
#define PB_THREADS (PB_WARPS * 32)
#define PB_BLOCKS  888        // 148 SMs * 6 resident blocks -> one wave

__device__ double       g_acc[2];        // [0]=sum (1-ciou)*w, [1]=sum dfl
__device__ unsigned int g_done;
__device__ unsigned int g_flags;         // bit0=any nonzero, bit1=not-int, bit2=not-float
__device__ int          g_fg_count;
__device__ int          g_fg_idx[532480]; // fg anchor indices (2 MB, >= max BA)

// --------------------------- 1) init ---------------------------------------
__global__ void init_kernel()
{
    g_acc[0] = 0.0; g_acc[1] = 0.0;
    g_done = 0u; g_flags = 0u; g_fg_count = 0;
}

// --------------------------- 2) detect -------------------------------------
// Scan min-footprint (BA bytes = BA/4 words): in-bounds for every candidate
// dtype. Bool-bytes is the safe fallback.
__global__ void detect_kernel(const unsigned int* __restrict__ mw, int nwords)
{
    unsigned int f = 0u;
    for (int i = blockIdx.x * blockDim.x + threadIdx.x; i < nwords;
         i += gridDim.x * blockDim.x) {
        unsigned int v = mw[i];
        if (v != 0u) f |= 1u;
        if (v > 1u)  f |= 2u;
        float x = __uint_as_float(v);
        if (!(x == 0.0f || x == 1.0f)) f |= 4u;
    }
    // warp OR then one atomic per warp (cheap, few hundred atomics total)
    #pragma unroll
    for (int o = 16; o; o >>= 1) f |= __shfl_xor_sync(0xffffffffu, f, o);
    if ((threadIdx.x & 31) == 0 && f) atomicOr(&g_flags, f);
}

__device__ __forceinline__ int derive_mode(unsigned int f)
{
    // 0 = int32, 1 = float32, 2 = bool bytes
    if (!(f & 1u)) return 2;       // all zero -> bool interpretation is safe
    if (!(f & 2u)) return 0;       // every word in {0,1} -> int32
    if (!(f & 4u)) return 1;       // every word in {0.0f,1.0f} -> float32
    return 2;                      // packed bytes -> bool
}

// --------------------------- 3) compact ------------------------------------
// Each thread owns 4 consecutive anchors; warp-aggregated atomic append.
__global__ __launch_bounds__(CB_THREADS)
void compact_kernel(const void* __restrict__ fg_mask, int nwords)
{
    const int mode = derive_mode(g_flags);
    const int lane = threadIdx.x & 31;
    const int i = blockIdx.x * blockDim.x + threadIdx.x;   // word index

    int f0 = 0, f1 = 0, f2 = 0, f3 = 0;
    if (i < nwords) {
        if (mode == 2) {
            uchar4 v = ((const uchar4*)fg_mask)[i];
            f0 = v.x != 0; f1 = v.y != 0; f2 = v.z != 0; f3 = v.w != 0;
        } else if (mode == 0) {
            int4 v = ((const int4*)fg_mask)[i];
            f0 = v.x != 0; f1 = v.y != 0; f2 = v.z != 0; f3 = v.w != 0;
        } else {
            float4 v = ((const float4*)fg_mask)[i];
            f0 = v.x != 0.f; f1 = v.y != 0.f; f2 = v.z != 0.f; f3 = v.w != 0.f;
        }
    }
    int cnt = f0 + f1 + f2 + f3;

    // warp inclusive scan of cnt
    int inc = cnt;
    #pragma unroll
    for (int o = 1; o < 32; o <<= 1) {
        int v = __shfl_up_sync(0xffffffffu, inc, o);
        if (lane >= o) inc += v;
    }
    int total = __shfl_sync(0xffffffffu, inc, 31);
    int base = 0;
    if (lane == 31 && total) base = atomicAdd(&g_fg_count, total);
    base = __shfl_sync(0xffffffffu, base, 31);

    int off = base + inc - cnt;
    int n = i << 2;
    if (f0) g_fg_idx[off++] = n + 0;
    if (f1) g_fg_idx[off++] = n + 1;
    if (f2) g_fg_idx[off++] = n + 2;
    if (f3) g_fg_idx[off++] = n + 3;
}

// --------------------------- 4) process ------------------------------------
__global__ __launch_bounds__(PB_THREADS)
void process_kernel(const float* __restrict__ pred_dist,
                    const float* __restrict__ pred_bboxes,
                    const float* __restrict__ anchor_points,
                    const float* __restrict__ target_bboxes,
                    const float* __restrict__ target_scores,
                    const float* __restrict__ tss,
                    float*       __restrict__ out,
                    int A, int out_size)
{
    const int lane  = threadIdx.x & 31;
    const int wid   = threadIdx.x >> 5;
    const int gw    = blockIdx.x * PB_WARPS + wid;
    const int nwarp = gridDim.x * PB_WARPS;
    const int count = g_fg_count;

    double acc_iou = 0.0, acc_dfl = 0.0;

    for (int it = gw; it < count; it += nwarp) {
        const int n = g_fg_idx[it];
        const int a = n % A;

        // ---- issue all memory up-front for MLP ----
        float4 sq = make_float4(0.f, 0.f, 0.f, 0.f);
        if (lane < NC / 4)
            sq = ((const float4*)(target_scores + (size_t)n * NC))[lane];
        float4 dq = make_float4(0.f, 0.f, 0.f, 0.f);
        if (lane < 16)
            dq = ((const float4*)(pred_dist + (size_t)n * (4 * RM)))[lane];
        float4 bp  = ((const float4*)pred_bboxes)[n];
        float4 bt  = ((const float4*)target_bboxes)[n];
        float2 apt = ((const float2*)anchor_points)[a];

        // ---- weight = sum of 80 scores ----
        float wsum = (sq.x + sq.y) + (sq.z + sq.w);
        #pragma unroll
        for (int o = 16; o; o >>= 1)
            wsum += __shfl_xor_sync(0xffffffffu, wsum, o);

        // ---- DFL: lanes 0..15 hold 64 logits; 4-lane group = one ltrb side ----
        float x0 = dq.x, x1 = dq.y, x2 = dq.z, x3 = dq.w;
        float m = fmaxf(fmaxf(x0, x1), fmaxf(x2, x3));
        m = fmaxf(m, __shfl_xor_sync(0xffffffffu, m, 1, 4));
        m = fmaxf(m, __shfl_xor_sync(0xffffffffu, m, 2, 4));
        float se = expf(x0 - m) + expf(x1 - m) + expf(x2 - m) + expf(x3 - m);
        se += __shfl_xor_sync(0xffffffffu, se, 1, 4);
        se += __shfl_xor_sync(0xffffffffu, se, 2, 4);
        float logZ = m + logf(se);

        // target ltrb distance for this side, clipped to [0, RM-1-0.01]
        float tv0 = apt.x - bt.x, tv1 = apt.y - bt.y;
        float tv2 = bt.z - apt.x, tv3 = bt.w - apt.y;
        int   s = (lane >> 2) & 3;
        float t = (s == 0) ? tv0 : (s == 1) ? tv1 : (s == 2) ? tv2 : tv3;
        t = fminf(fmaxf(t, 0.0f), (float)(RM - 1) - 0.01f);
        int   tl = (int)t;
        int   tr = min(tl + 1, RM - 1);
        float wl = (float)(tl + 1) - t;
        float wr = 1.0f - wl;

        // select logits at tl/tr inside the 4-lane group (each lane owns 4 bins)
        int base = (lane & 3) * 4;
        int dl = tl - base, dr = tr - base;
        float xl = 0.f, xr = 0.f;
        if (dl >= 0 && dl < 4) xl = (dl == 0) ? x0 : (dl == 1) ? x1 : (dl == 2) ? x2 : x3;
        if (dr >= 0 && dr < 4) xr = (dr == 0) ? x0 : (dr == 1) ? x1 : (dr == 2) ? x2 : x3;
        xl += __shfl_xor_sync(0xffffffffu, xl, 1, 4);
        xl += __shfl_xor_sync(0xffffffffu, xl, 2, 4);
        xr += __shfl_xor_sync(0xffffffffu, xr, 1, 4);
        xr += __shfl_xor_sync(0xffffffffu, xr, 2, 4);

        // dfl_side = logZ - (x_tl*wl + x_tr*wr)
        float dfl_side = logZ - (xl * wl + xr * wr);
        float dc = (lane < 16 && (lane & 3) == 0) ? dfl_side : 0.f;
        #pragma unroll
        for (int o = 16; o; o >>= 1)
            dc += __shfl_xor_sync(0xffffffffu, dc, o);

        // ---- CIoU on lane 0 ----
        if (lane == 0) {
            float x11 = bp.x, y11 = bp.y, x21 = bp.z, y21 = bp.w;
            float x12 = bt.x, y12 = bt.y, x22 = bt.z, y22 = bt.w;
            float iw = fmaxf(fminf(x21, x22) - fmaxf(x11, x12), 0.f);
            float ih = fmaxf(fminf(y21, y22) - fmaxf(y11, y12), 0.f);
            float inter = iw * ih;
            float w1 = x21 - x11, h1 = y21 - y11;
            float w2 = x22 - x12, h2 = y22 - y12;
            float uni = w1 * h1 + w2 * h2 - inter + EPSF;
            float iou = inter / uni;
            float cw = fmaxf(x21, x22) - fminf(x11, x12);
            float ch = fmaxf(y21, y22) - fminf(y11, y12);
            float c2 = cw * cw + ch * ch + EPSF;
            float dx = x11 + x21 - x12 - x22;
            float dy = y11 + y21 - y12 - y22;
            float rho2 = (dx * dx + dy * dy) * 0.25f;
            float dat = atanf(w1 / (h1 + EPSF)) - atanf(w2 / (h2 + EPSF));
            float v = FOUR_OVER_PI2 * dat * dat;
            float alpha = v / (1.0f - iou + v + EPSF);
            float ciou = iou - (rho2 / c2 + v * alpha);

            acc_iou += (double)((1.0f - ciou) * wsum);
            acc_dfl += (double)dc;
        }
    }

    // ---- block reduction + last-block finalize ----
    __shared__ double s0[PB_WARPS], s1[PB_WARPS];
    if (lane == 0) { s0[wid] = acc_iou; s1[wid] = acc_dfl; }
    __syncthreads();

    if (threadIdx.x == 0) {
        double a0 = 0, a1 = 0;
        #pragma unroll
        for (int i = 0; i < PB_WARPS; i++) { a0 += s0[i]; a1 += s1[i]; }
        if (a0 != 0.0) atomicAdd(&g_acc[0], a0);
        if (a1 != 0.0) atomicAdd(&g_acc[1], a1);
        __threadfence();
        unsigned int prev = atomicAdd(&g_done, 1u);
        if (prev == gridDim.x - 1) {
            double si  = *((volatile double*)&g_acc[0]);
            double sd  = *((volatile double*)&g_acc[1]);
            double nfg = (double)g_fg_count;
            double li = si / (double)tss[0];
            double ld = sd / fmax(nfg * 4.0, 1.0);
            if (out_size >= 1) out[0] = (float)li;
            if (out_size >= 2) out[1] = (float)ld;
        }
    }
}

// ---------------------------------------------------------------------------
// Launch. Inputs (metadata order): pred_dist, pred_bboxes, anchor_points,
// target_bboxes, target_scores, target_scores_sum, fg_mask.
// ---------------------------------------------------------------------------
extern "C" void kernel_launch(void* const* d_in, const int* in_sizes, int n_in,
                              void* d_out, int out_size)
{
    const float* pred_dist     = (const float*)d_in[0];
    const float* pred_bboxes   = (const float*)d_in[1];
    const float* anchor_points = (const float*)d_in[2];
    const float* target_bboxes = (const float*)d_in[3];
    const float* target_scores = (const float*)d_in[4];
    const float* tss           = (const float*)d_in[5];
    const void*  fg_mask       = (const void*)d_in[6];

    const int BA = in_sizes[6];        // B*A anchors (element count of fg_mask)
    const int A  = in_sizes[2] / 2;    // anchor_points is (A,2)
    const int nwords = BA >> 2;

    init_kernel<<<1, 1>>>();

    int dblocks = (nwords + CB_THREADS - 1) / CB_THREADS;
    if (dblocks > 296) dblocks = 296;
    detect_kernel<<<dblocks, CB_THREADS>>>((const unsigned int*)fg_mask, nwords);

    int cblocks = (nwords + CB_THREADS - 1) / CB_THREADS;
    compact_kernel<<<cblocks, CB_THREADS>>>(fg_mask, nwords);

    process_kernel<<<PB_BLOCKS, PB_THREADS>>>(
        pred_dist, pred_bboxes, anchor_points, target_bboxes, target_scores,
        tss, (float*)d_out, A, out_size);
}

// round 3
// speedup vs baseline: 1.7585x; 1.0801x over previous
#include <cuda_runtime.h>
#include <math.h>

// ---------------------------------------------------------------------------
// BboxLoss (CIoU + DFL), B=32, A=8400, RM=16, NC=80.
// R3: 3 launches (detect, compact, process). Process uses 8 lanes per fg
// anchor (4 anchors/warp), base-2 softmax, self-resetting globals.
// ---------------------------------------------------------------------------

#define EPSF 1e-7f
#define FOUR_OVER_PI2 0.40528473456935108577f   // 4 / pi^2
#define L2E 1.4426950408889634074f              // log2(e)
#define LN2 0.69314718055994530942f             // ln(2)
#define RM 16
#define NC 80

#define CB_THREADS 256
#define PB_WARPS   8
#define PB_THREADS (PB_WARPS * 32)
#define PB_BLOCKS  888

__device__ double       g_acc[2];        // [0]=sum (1-ciou)*w, [1]=sum dfl(base2)
__device__ unsigned int g_done;
__device__ unsigned int g_flags;         // bit0=any nonzero, bit1=not-int, bit2=not-float
__device__ int          g_fg_count;
__device__ int          g_fg_idx[532480];

// --------------------------- 1) detect -------------------------------------
// Classify fg_mask storage dtype. Scans min-footprint (BA bytes = BA/4 words)
// so it is in-bounds for every candidate dtype. Relies on g_flags == 0 at
// entry (static init on first call; self-reset by process finalize after).
__global__ void detect_kernel(const unsigned int* __restrict__ mw, int nwords)
{
    unsigned int f = 0u;
    for (int i = blockIdx.x * blockDim.x + threadIdx.x; i < nwords;
         i += gridDim.x * blockDim.x) {
        unsigned int v = mw[i];
        if (v != 0u) f |= 1u;
        if (v > 1u)  f |= 2u;
        float x = __uint_as_float(v);
        if (!(x == 0.0f || x == 1.0f)) f |= 4u;
    }
    #pragma unroll
    for (int o = 16; o; o >>= 1) f |= __shfl_xor_sync(0xffffffffu, f, o);
    if ((threadIdx.x & 31) == 0 && f) atomicOr(&g_flags, f);
}

__device__ __forceinline__ int derive_mode(unsigned int f)
{
    // 0 = int32, 1 = float32, 2 = bool bytes
    if (!(f & 1u)) return 2;
    if (!(f & 2u)) return 0;
    if (!(f & 4u)) return 1;
    return 2;
}

// --------------------------- 2) compact ------------------------------------
__global__ __launch_bounds__(CB_THREADS)
void compact_kernel(const void* __restrict__ fg_mask, int nwords)
{
    const int mode = derive_mode(g_flags);
    const int lane = threadIdx.x & 31;
    const int i = blockIdx.x * blockDim.x + threadIdx.x;

    int f0 = 0, f1 = 0, f2 = 0, f3 = 0;
    if (i < nwords) {
        if (mode == 2) {
            uchar4 v = ((const uchar4*)fg_mask)[i];
            f0 = v.x != 0; f1 = v.y != 0; f2 = v.z != 0; f3 = v.w != 0;
        } else if (mode == 0) {
            int4 v = ((const int4*)fg_mask)[i];
            f0 = v.x != 0; f1 = v.y != 0; f2 = v.z != 0; f3 = v.w != 0;
        } else {
            float4 v = ((const float4*)fg_mask)[i];
            f0 = v.x != 0.f; f1 = v.y != 0.f; f2 = v.z != 0.f; f3 = v.w != 0.f;
        }
    }
    int cnt = f0 + f1 + f2 + f3;

    int inc = cnt;
    #pragma unroll
    for (int o = 1; o < 32; o <<= 1) {
        int v = __shfl_up_sync(0xffffffffu, inc, o);
        if (lane >= o) inc += v;
    }
    int total = __shfl_sync(0xffffffffu, inc, 31);
    int base = 0;
    if (lane == 31 && total) base = atomicAdd(&g_fg_count, total);
    base = __shfl_sync(0xffffffffu, base, 31);

    int off = base + inc - cnt;
    int n = i << 2;
    if (f0) g_fg_idx[off++] = n + 0;
    if (f1) g_fg_idx[off++] = n + 1;
    if (f2) g_fg_idx[off++] = n + 2;
    if (f3) g_fg_idx[off++] = n + 3;
}

// --------------------------- 3) process ------------------------------------
// 8 lanes per anchor, 4 anchors per warp. Lane layout within a group
// (gl = lane & 7): side s = gl>>1 (l,t,r,b); sub = gl&1 owns 8 of the side's
// 16 logits. Softmax done in base-2; final DFL scaled by ln2.
__global__ __launch_bounds__(PB_THREADS)
void process_kernel(const float* __restrict__ pred_dist,
                    const float* __restrict__ pred_bboxes,
                    const float* __restrict__ anchor_points,
                    const float* __restrict__ target_bboxes,
                    const float* __restrict__ target_scores,
                    const float* __restrict__ tss,
                    float*       __restrict__ out,
                    int A, int out_size)
{
    const int lane  = threadIdx.x & 31;
    const int wid   = threadIdx.x >> 5;
    const int group = lane >> 3;
    const int gl    = lane & 7;
    const int gw    = blockIdx.x * PB_WARPS + wid;
    const int nwarp = gridDim.x * PB_WARPS;
    const int count = g_fg_count;
    const unsigned int FULL = 0xffffffffu;

    double acc_iou = 0.0, acc_dfl = 0.0;

    for (int base_slot = gw * 4; base_slot < count; base_slot += nwarp * 4) {
        const int  slot   = base_slot + group;
        const bool active = slot < count;
        const int  n      = active ? g_fg_idx[slot] : 0;

        // ---- issue all loads up-front ----
        float4 sq0 = make_float4(0,0,0,0), sq1 = make_float4(0,0,0,0);
        float4 sq2 = make_float4(0,0,0,0);
        float4 dq0 = make_float4(0,0,0,0), dq1 = make_float4(0,0,0,0);
        float4 bt  = make_float4(0,0,0,0), bp = make_float4(0,0,0,0);
        float2 apt = make_float2(0,0);
        if (active) {
            const int a = n % A;
            const float4* srow = (const float4*)(target_scores + (size_t)n * NC);
            const float4* drow = (const float4*)(pred_dist + (size_t)n * (4 * RM));
            sq0 = srow[gl];
            sq1 = srow[gl + 8];
            if (gl < 4) sq2 = srow[gl + 16];
            dq0 = drow[gl * 2];
            dq1 = drow[gl * 2 + 1];
            bt  = ((const float4*)target_bboxes)[n];
            apt = ((const float2*)anchor_points)[a];
            if (gl == 0) bp = ((const float4*)pred_bboxes)[n];
        }

        // ---- weight = sum of 80 scores (width-8 reduce) ----
        float ws = ((sq0.x + sq0.y) + (sq0.z + sq0.w))
                 + ((sq1.x + sq1.y) + (sq1.z + sq1.w))
                 + ((sq2.x + sq2.y) + (sq2.z + sq2.w));
        ws += __shfl_xor_sync(FULL, ws, 1, 8);
        ws += __shfl_xor_sync(FULL, ws, 2, 8);
        ws += __shfl_xor_sync(FULL, ws, 4, 8);

        // ---- base-2 log-softmax over this side's 16 logits ----
        float y[8];
        y[0] = dq0.x * L2E; y[1] = dq0.y * L2E; y[2] = dq0.z * L2E; y[3] = dq0.w * L2E;
        y[4] = dq1.x * L2E; y[5] = dq1.y * L2E; y[6] = dq1.z * L2E; y[7] = dq1.w * L2E;
        float m = y[0];
        #pragma unroll
        for (int k = 1; k < 8; k++) m = fmaxf(m, y[k]);
        m = fmaxf(m, __shfl_xor_sync(FULL, m, 1, 2));
        float se = 0.0f;
        #pragma unroll
        for (int k = 0; k < 8; k++) se += exp2f(y[k] - m);
        se += __shfl_xor_sync(FULL, se, 1, 2);
        float logZ2 = m + log2f(se);

        // ---- target ltrb distance for this side ----
        const int   s  = gl >> 1;
        float t = (s == 0) ? (apt.x - bt.x)
                : (s == 1) ? (apt.y - bt.y)
                : (s == 2) ? (bt.z - apt.x)
                :            (bt.w - apt.y);
        t = fminf(fmaxf(t, 0.0f), (float)(RM - 1) - 0.01f);
        const int   tl = (int)t;
        const int   tr = min(tl + 1, RM - 1);
        const float wl = (float)(tl + 1) - t;
        const float wr = 1.0f - wl;

        // pick y at tl/tr (each lane owns bins [bofs, bofs+8))
        const int bofs = (gl & 1) * 8;
        float yl = 0.0f, yr = 0.0f;
        #pragma unroll
        for (int k = 0; k < 8; k++) {
            yl = (tl - bofs == k) ? y[k] : yl;
            yr = (tr - bofs == k) ? y[k] : yr;
        }
        yl += __shfl_xor_sync(FULL, yl, 1, 2);
        yr += __shfl_xor_sync(FULL, yr, 1, 2);

        // dfl (base-2 units) for this side; sum the 4 side leaders (gl even)
        float dfl2 = logZ2 - (yl * wl + yr * wr);
        float dc = (((gl & 1) == 0) && active) ? dfl2 : 0.0f;
        dc += __shfl_xor_sync(FULL, dc, 2, 8);
        dc += __shfl_xor_sync(FULL, dc, 4, 8);

        // ---- CIoU on group leader ----
        if (gl == 0 && active) {
            float x11 = bp.x, y11 = bp.y, x21 = bp.z, y21 = bp.w;
            float x12 = bt.x, y12 = bt.y, x22 = bt.z, y22 = bt.w;
            float iw = fmaxf(fminf(x21, x22) - fmaxf(x11, x12), 0.f);
            float ih = fmaxf(fminf(y21, y22) - fmaxf(y11, y12), 0.f);
            float inter = iw * ih;
            float w1 = x21 - x11, h1 = y21 - y11;
            float w2 = x22 - x12, h2 = y22 - y12;
            float uni = w1 * h1 + w2 * h2 - inter + EPSF;
            float iou = inter / uni;
            float cw = fmaxf(x21, x22) - fminf(x11, x12);
            float ch = fmaxf(y21, y22) - fminf(y11, y12);
            float c2 = cw * cw + ch * ch + EPSF;
            float dx = x11 + x21 - x12 - x22;
            float dy = y11 + y21 - y12 - y22;
            float rho2 = (dx * dx + dy * dy) * 0.25f;
            float dat = atanf(w1 / (h1 + EPSF)) - atanf(w2 / (h2 + EPSF));
            float v = FOUR_OVER_PI2 * dat * dat;
            float alpha = v / (1.0f - iou + v + EPSF);
            float ciou = iou - (rho2 / c2 + v * alpha);

            acc_iou += (double)((1.0f - ciou) * ws);
            acc_dfl += (double)dc;              // still in base-2 units
        }
    }

    // ---- warp reduce (doubles), then block reduce + last-block finalize ----
    #pragma unroll
    for (int o = 16; o; o >>= 1) {
        acc_iou += __shfl_xor_sync(0xffffffffu, acc_iou, o);
        acc_dfl += __shfl_xor_sync(0xffffffffu, acc_dfl, o);
    }

    __shared__ double s0[PB_WARPS], s1[PB_WARPS];
    if (lane == 0) { s0[wid] = acc_iou; s1[wid] = acc_dfl; }
    __syncthreads();

    if (threadIdx.x == 0) {
        double a0 = 0, a1 = 0;
        #pragma unroll
        for (int i = 0; i < PB_WARPS; i++) { a0 += s0[i]; a1 += s1[i]; }
        if (a0 != 0.0) atomicAdd(&g_acc[0], a0);
        if (a1 != 0.0) atomicAdd(&g_acc[1], a1);
        __threadfence();
        unsigned int prev = atomicAdd(&g_done, 1u);
        if (prev == gridDim.x - 1) {
            double si  = *((volatile double*)&g_acc[0]);
            double sd  = *((volatile double*)&g_acc[1]) * (double)LN2;
            double nfg = (double)g_fg_count;
            double li = si / (double)tss[0];
            double ld = sd / fmax(nfg * 4.0, 1.0);
            if (out_size >= 1) out[0] = (float)li;
            if (out_size >= 2) out[1] = (float)ld;
            // self-reset for the next graph replay
            g_acc[0] = 0.0; g_acc[1] = 0.0;
            g_done = 0u; g_flags = 0u; g_fg_count = 0;
        }
    }
}

// ---------------------------------------------------------------------------
// Launch. Inputs (metadata order): pred_dist, pred_bboxes, anchor_points,
// target_bboxes, target_scores, target_scores_sum, fg_mask.
// ---------------------------------------------------------------------------
extern "C" void kernel_launch(void* const* d_in, const int* in_sizes, int n_in,
                              void* d_out, int out_size)
{
    const float* pred_dist     = (const float*)d_in[0];
    const float* pred_bboxes   = (const float*)d_in[1];
    const float* anchor_points = (const float*)d_in[2];
    const float* target_bboxes = (const float*)d_in[3];
    const float* target_scores = (const float*)d_in[4];
    const float* tss           = (const float*)d_in[5];
    const void*  fg_mask       = (const void*)d_in[6];

    const int BA = in_sizes[6];
    const int A  = in_sizes[2] / 2;
    const int nwords = BA >> 2;

    int dblocks = (nwords + CB_THREADS - 1) / CB_THREADS;
    if (dblocks > 296) dblocks = 296;
    detect_kernel<<<dblocks, CB_THREADS>>>((const unsigned int*)fg_mask, nwords);

    int cblocks = (nwords + CB_THREADS - 1) / CB_THREADS;
    compact_kernel<<<cblocks, CB_THREADS>>>(fg_mask, nwords);

    process_kernel<<<PB_BLOCKS, PB_THREADS>>>(
        pred_dist, pred_bboxes, anchor_points, target_bboxes, target_scores,
        tss, (float*)d_out, A, out_size);
}

// round 4
// speedup vs baseline: 1.8759x; 1.0667x over previous
#include <cuda_runtime.h>
#include <math.h>

// ---------------------------------------------------------------------------
// BboxLoss (CIoU + DFL), B=32, A=8400, RM=16, NC=80.
// R4: single persistent kernel, software grid barriers between phases:
//   phase 1: detect fg_mask storage dtype (bool bytes / int32 / float32)
//   phase 2: stream-compact fg anchor indices (mask L2-hot from phase 1)
//   phase 3: warp-per-4-anchors loss computation (8 lanes per anchor)
//   finalize: block 0 writes outputs, self-resets globals for next replay.
// Grid barriers use monotonic per-phase counters (no reset needed across
// graph replays). Co-residency guaranteed by __launch_bounds__(256, 4) with
// grid = 148 * 4 = 592 blocks.
// ---------------------------------------------------------------------------

#define EPSF 1e-7f
#define FOUR_OVER_PI2 0.40528473456935108577f   // 4 / pi^2
#define L2E 1.4426950408889634074f              // log2(e)
#define LN2 0.69314718055994530942f             // ln(2)
#define RM 16
#define NC 80

#define NBLOCKS 592
#define NTHREADS 256
#define NWARPS (NTHREADS / 32)

__device__ double       g_acc[2];         // [0]=sum (1-ciou)*w, [1]=sum dfl(base2)
__device__ unsigned int g_flags;          // bit0=any nonzero, bit1=not-int, bit2=not-float
__device__ int          g_fg_count;
__device__ unsigned int g_bar[3];         // monotonic phase barriers
__device__ int          g_fg_idx[532480];

// Monotonic grid barrier: deadlock-free given all blocks co-resident.
// Counter never resets; target derived from the arrival epoch.
__device__ __forceinline__ void grid_barrier(int phase)
{
    __syncthreads();
    if (threadIdx.x == 0) {
        __threadfence();
        unsigned int old = atomicAdd(&g_bar[phase], 1u);
        unsigned int target = (old / NBLOCKS) * NBLOCKS + NBLOCKS;
        while ((int)(*(volatile unsigned int*)&g_bar[phase] - target) < 0) {
            __nanosleep(60);
        }
    }
    __syncthreads();
    __threadfence();
}

__global__ __launch_bounds__(NTHREADS, 4)
void fused_bbox_loss(const float* __restrict__ pred_dist,
                     const float* __restrict__ pred_bboxes,
                     const float* __restrict__ anchor_points,
                     const float* __restrict__ target_bboxes,
                     const float* __restrict__ target_scores,
                     const float* __restrict__ tss,
                     const void*  __restrict__ fg_mask,
                     float*       __restrict__ out,
                     int nwords, int A, int out_size)
{
    const int tid   = blockIdx.x * NTHREADS + threadIdx.x;
    const int nthr  = NBLOCKS * NTHREADS;
    const int lane  = threadIdx.x & 31;
    const int wid   = threadIdx.x >> 5;
    const unsigned int FULL = 0xffffffffu;

    // ============== phase 1: detect mask dtype =============================
    // Scan min-footprint (BA bytes = nwords u32 words): in-bounds for every
    // candidate dtype. Bool bytes is the safe fallback.
    {
        unsigned int f = 0u;
        for (int i = tid; i < nwords; i += nthr) {
            unsigned int v = ((const unsigned int*)fg_mask)[i];
            if (v != 0u) f |= 1u;
            if (v > 1u)  f |= 2u;
            float x = __uint_as_float(v);
            if (!(x == 0.0f || x == 1.0f)) f |= 4u;
        }
        #pragma unroll
        for (int o = 16; o; o >>= 1) f |= __shfl_xor_sync(FULL, f, o);
        if (lane == 0 && f) atomicOr(&g_flags, f);
    }
    grid_barrier(0);

    // ============== phase 2: compact fg indices ============================
    {
        const unsigned int fl = *(volatile unsigned int*)&g_flags;
        // mode: 0 = int32, 1 = float32, 2 = bool bytes
        int mode;
        if (!(fl & 1u))      mode = 2;   // all zero -> bool is safe
        else if (!(fl & 2u)) mode = 0;   // words all in {0,1} -> int32
        else if (!(fl & 4u)) mode = 1;   // words all in {0.f,1.f} -> float32
        else                 mode = 2;   // packed bytes -> bool

        for (int i = tid; i < ((nwords + nthr - 1) / nthr) * nthr; i += nthr) {
            int f0 = 0, f1 = 0, f2 = 0, f3 = 0;
            if (i < nwords) {
                if (mode == 2) {
                    uchar4 v = ((const uchar4*)fg_mask)[i];
                    f0 = v.x != 0; f1 = v.y != 0; f2 = v.z != 0; f3 = v.w != 0;
                } else if (mode == 0) {
                    int4 v = ((const int4*)fg_mask)[i];
                    f0 = v.x != 0; f1 = v.y != 0; f2 = v.z != 0; f3 = v.w != 0;
                } else {
                    float4 v = ((const float4*)fg_mask)[i];
                    f0 = v.x != 0.f; f1 = v.y != 0.f; f2 = v.z != 0.f; f3 = v.w != 0.f;
                }
            }
            int cnt = f0 + f1 + f2 + f3;

            int inc = cnt;
            #pragma unroll
            for (int o = 1; o < 32; o <<= 1) {
                int v = __shfl_up_sync(FULL, inc, o);
                if (lane >= o) inc += v;
            }
            int total = __shfl_sync(FULL, inc, 31);
            int base = 0;
            if (lane == 31 && total) base = atomicAdd(&g_fg_count, total);
            base = __shfl_sync(FULL, base, 31);

            int off = base + inc - cnt;
            int n = i << 2;
            if (f0) g_fg_idx[off++] = n + 0;
            if (f1) g_fg_idx[off++] = n + 1;
            if (f2) g_fg_idx[off++] = n + 2;
            if (f3) g_fg_idx[off++] = n + 3;
        }
    }
    grid_barrier(1);

    // ============== phase 3: process fg anchors ============================
    // 8 lanes per anchor, 4 anchors per warp. gl = lane&7; side s = gl>>1
    // (l,t,r,b); sub = gl&1 owns 8 of the side's 16 logits. Base-2 softmax.
    const int count = *(volatile int*)&g_fg_count;
    const int group = lane >> 3;
    const int gl    = lane & 7;
    const int gw    = blockIdx.x * NWARPS + wid;
    const int nwarp = NBLOCKS * NWARPS;

    double acc_iou = 0.0, acc_dfl = 0.0;

    for (int base_slot = gw * 4; base_slot < count; base_slot += nwarp * 4) {
        const int  slot   = base_slot + group;
        const bool active = slot < count;
        const int  n      = active ? g_fg_idx[slot] : 0;

        float4 sq0 = make_float4(0,0,0,0), sq1 = make_float4(0,0,0,0);
        float4 sq2 = make_float4(0,0,0,0);
        float4 dq0 = make_float4(0,0,0,0), dq1 = make_float4(0,0,0,0);
        float4 bt  = make_float4(0,0,0,0), bp = make_float4(0,0,0,0);
        float2 apt = make_float2(0,0);
        if (active) {
            const int a = n % A;
            const float4* srow = (const float4*)(target_scores + (size_t)n * NC);
            const float4* drow = (const float4*)(pred_dist + (size_t)n * (4 * RM));
            sq0 = srow[gl];
            sq1 = srow[gl + 8];
            if (gl < 4) sq2 = srow[gl + 16];
            dq0 = drow[gl * 2];
            dq1 = drow[gl * 2 + 1];
            bt  = ((const float4*)target_bboxes)[n];
            apt = ((const float2*)anchor_points)[a];
            if (gl == 0) bp = ((const float4*)pred_bboxes)[n];
        }

        // weight = sum of 80 scores (width-8 reduce)
        float ws = ((sq0.x + sq0.y) + (sq0.z + sq0.w))
                 + ((sq1.x + sq1.y) + (sq1.z + sq1.w))
                 + ((sq2.x + sq2.y) + (sq2.z + sq2.w));
        ws += __shfl_xor_sync(FULL, ws, 1, 8);
        ws += __shfl_xor_sync(FULL, ws, 2, 8);
        ws += __shfl_xor_sync(FULL, ws, 4, 8);

        // base-2 log-softmax over this side's 16 logits
        float y[8];
        y[0] = dq0.x * L2E; y[1] = dq0.y * L2E; y[2] = dq0.z * L2E; y[3] = dq0.w * L2E;
        y[4] = dq1.x * L2E; y[5] = dq1.y * L2E; y[6] = dq1.z * L2E; y[7] = dq1.w * L2E;
        float m = y[0];
        #pragma unroll
        for (int k = 1; k < 8; k++) m = fmaxf(m, y[k]);
        m = fmaxf(m, __shfl_xor_sync(FULL, m, 1, 2));
        float se = 0.0f;
        #pragma unroll
        for (int k = 0; k < 8; k++) se += exp2f(y[k] - m);
        se += __shfl_xor_sync(FULL, se, 1, 2);
        float logZ2 = m + log2f(se);

        // target ltrb distance for this side, clipped to [0, RM-1-0.01]
        const int s = gl >> 1;
        float t = (s == 0) ? (apt.x - bt.x)
                : (s == 1) ? (apt.y - bt.y)
                : (s == 2) ? (bt.z - apt.x)
                :            (bt.w - apt.y);
        t = fminf(fmaxf(t, 0.0f), (float)(RM - 1) - 0.01f);
        const int   tl = (int)t;
        const int   tr = min(tl + 1, RM - 1);
        const float wl = (float)(tl + 1) - t;
        const float wr = 1.0f - wl;

        // pick y at tl/tr (this lane owns bins [bofs, bofs+8))
        const int bofs = (gl & 1) * 8;
        float yl = 0.0f, yr = 0.0f;
        #pragma unroll
        for (int k = 0; k < 8; k++) {
            yl = (tl - bofs == k) ? y[k] : yl;
            yr = (tr - bofs == k) ? y[k] : yr;
        }
        yl += __shfl_xor_sync(FULL, yl, 1, 2);
        yr += __shfl_xor_sync(FULL, yr, 1, 2);

        // dfl (base-2 units) for this side; sum across the 4 side leaders
        float dfl2 = logZ2 - (yl * wl + yr * wr);
        float dc = (((gl & 1) == 0) && active) ? dfl2 : 0.0f;
        dc += __shfl_xor_sync(FULL, dc, 2, 8);
        dc += __shfl_xor_sync(FULL, dc, 4, 8);

        // CIoU on group leader
        if (gl == 0 && active) {
            float x11 = bp.x, y11 = bp.y, x21 = bp.z, y21 = bp.w;
            float x12 = bt.x, y12 = bt.y, x22 = bt.z, y22 = bt.w;
            float iw = fmaxf(fminf(x21, x22) - fmaxf(x11, x12), 0.f);
            float ih = fmaxf(fminf(y21, y22) - fmaxf(y11, y12), 0.f);
            float inter = iw * ih;
            float w1 = x21 - x11, h1 = y21 - y11;
            float w2 = x22 - x12, h2 = y22 - y12;
            float uni = w1 * h1 + w2 * h2 - inter + EPSF;
            float iou = inter / uni;
            float cw = fmaxf(x21, x22) - fminf(x11, x12);
            float ch = fmaxf(y21, y22) - fminf(y11, y12);
            float c2 = cw * cw + ch * ch + EPSF;
            float dx = x11 + x21 - x12 - x22;
            float dy = y11 + y21 - y12 - y22;
            float rho2 = (dx * dx + dy * dy) * 0.25f;
            float dat = atanf(w1 / (h1 + EPSF)) - atanf(w2 / (h2 + EPSF));
            float v = FOUR_OVER_PI2 * dat * dat;
            float alpha = v / (1.0f - iou + v + EPSF);
            float ciou = iou - (rho2 / c2 + v * alpha);

            acc_iou += (double)((1.0f - ciou) * ws);
            acc_dfl += (double)dc;              // base-2 units
        }
    }

    // warp reduce (doubles), block reduce, global atomics
    #pragma unroll
    for (int o = 16; o; o >>= 1) {
        acc_iou += __shfl_xor_sync(FULL, acc_iou, o);
        acc_dfl += __shfl_xor_sync(FULL, acc_dfl, o);
    }
    __shared__ double s0[NWARPS], s1[NWARPS];
    if (lane == 0) { s0[wid] = acc_iou; s1[wid] = acc_dfl; }
    __syncthreads();
    if (threadIdx.x == 0) {
        double a0 = 0, a1 = 0;
        #pragma unroll
        for (int i = 0; i < NWARPS; i++) { a0 += s0[i]; a1 += s1[i]; }
        if (a0 != 0.0) atomicAdd(&g_acc[0], a0);
        if (a1 != 0.0) atomicAdd(&g_acc[1], a1);
    }

    grid_barrier(2);

    // ============== finalize (block 0) + self-reset ========================
    if (blockIdx.x == 0 && threadIdx.x == 0) {
        double si  = *(volatile double*)&g_acc[0];
        double sd  = *(volatile double*)&g_acc[1] * (double)LN2;
        double nfg = (double)count;
        double li = si / (double)tss[0];
        double ld = sd / fmax(nfg * 4.0, 1.0);
        if (out_size >= 1) out[0] = (float)li;
        if (out_size >= 2) out[1] = (float)ld;
        // reset for next graph replay (all blocks past barrier 2; any block
        // still exiting no longer reads these). Barrier counters are
        // monotonic and never reset.
        g_acc[0] = 0.0; g_acc[1] = 0.0;
        g_flags = 0u; g_fg_count = 0;
    }
}

// ---------------------------------------------------------------------------
// Launch. Inputs (metadata order): pred_dist, pred_bboxes, anchor_points,
// target_bboxes, target_scores, target_scores_sum, fg_mask.
// ---------------------------------------------------------------------------
extern "C" void kernel_launch(void* const* d_in, const int* in_sizes, int n_in,
                              void* d_out, int out_size)
{
    const float* pred_dist     = (const float*)d_in[0];
    const float* pred_bboxes   = (const float*)d_in[1];
    const float* anchor_points = (const float*)d_in[2];
    const float* target_bboxes = (const float*)d_in[3];
    const float* target_scores = (const float*)d_in[4];
    const float* tss           = (const float*)d_in[5];
    const void*  fg_mask       = (const void*)d_in[6];

    const int BA = in_sizes[6];        // B*A anchors
    const int A  = in_sizes[2] / 2;    // anchor_points is (A,2)

    fused_bbox_loss<<<NBLOCKS, NTHREADS>>>(
        pred_dist, pred_bboxes, anchor_points, target_bboxes, target_scores,
        tss, fg_mask, (float*)d_out, BA >> 2, A, out_size);
}

// round 5
// speedup vs baseline: 2.0460x; 1.0907x over previous
#include <cuda_runtime.h>
#include <math.h>

// ---------------------------------------------------------------------------
// BboxLoss (CIoU + DFL), B=32, A=8400, RM=16, NC=80.
// R5: persistent kernel (detect -> compact -> process). Process phase stages
// each anchor batch into shared memory via cp.async (register-free MLP: all
// gathered rows for a warp's 4 anchors are in flight before the first wait),
// then computes with the 8-lanes-per-anchor scheme from smem.
// ---------------------------------------------------------------------------

#define EPSF 1e-7f
#define FOUR_OVER_PI2 0.40528473456935108577f   // 4 / pi^2
#define L2E 1.4426950408889634074f              // log2(e)
#define LN2 0.69314718055994530942f             // ln(2)
#define RM 16
#define NC 80

#define NBLOCKS 592
#define NTHREADS 256
#define NWARPS (NTHREADS / 32)
#define ANCH_F 168                               // floats per staged anchor (672B)

__device__ double       g_acc[2];         // [0]=sum (1-ciou)*w, [1]=sum dfl(base2)
__device__ unsigned int g_flags;          // bit0=any nonzero, bit1=not-int, bit2=not-float
__device__ int          g_fg_count;
__device__ unsigned int g_bar[3];         // monotonic phase barriers
__device__ int          g_fg_idx[532480];

__device__ __forceinline__ void cp16(unsigned int s, const void* g) {
    asm volatile("cp.async.cg.shared.global [%0], [%1], 16;" :: "r"(s), "l"(g));
}
__device__ __forceinline__ void cp8(unsigned int s, const void* g) {
    asm volatile("cp.async.ca.shared.global [%0], [%1], 8;" :: "r"(s), "l"(g));
}
__device__ __forceinline__ void cp_wait_all() {
    asm volatile("cp.async.wait_all;" ::: "memory");
}

// Monotonic grid barrier: deadlock-free given all blocks co-resident.
__device__ __forceinline__ void grid_barrier(int phase)
{
    __syncthreads();
    if (threadIdx.x == 0) {
        __threadfence();
        unsigned int old = atomicAdd(&g_bar[phase], 1u);
        unsigned int target = (old / NBLOCKS) * NBLOCKS + NBLOCKS;
        while ((int)(*(volatile unsigned int*)&g_bar[phase] - target) < 0) {
            __nanosleep(60);
        }
    }
    __syncthreads();
    __threadfence();
}

__global__ __launch_bounds__(NTHREADS, 4)
void fused_bbox_loss(const float* __restrict__ pred_dist,
                     const float* __restrict__ pred_bboxes,
                     const float* __restrict__ anchor_points,
                     const float* __restrict__ target_bboxes,
                     const float* __restrict__ target_scores,
                     const float* __restrict__ tss,
                     const void*  __restrict__ fg_mask,
                     float*       __restrict__ out,
                     int nwords, int A, int out_size)
{
    const int tid   = blockIdx.x * NTHREADS + threadIdx.x;
    const int nthr  = NBLOCKS * NTHREADS;
    const int lane  = threadIdx.x & 31;
    const int wid   = threadIdx.x >> 5;
    const unsigned int FULL = 0xffffffffu;

    // ============== phase 1: detect mask dtype =============================
    {
        unsigned int f = 0u;
        for (int i = tid; i < nwords; i += nthr) {
            unsigned int v = ((const unsigned int*)fg_mask)[i];
            if (v != 0u) f |= 1u;
            if (v > 1u)  f |= 2u;
            float x = __uint_as_float(v);
            if (!(x == 0.0f || x == 1.0f)) f |= 4u;
        }
        #pragma unroll
        for (int o = 16; o; o >>= 1) f |= __shfl_xor_sync(FULL, f, o);
        if (lane == 0 && f) atomicOr(&g_flags, f);
    }
    grid_barrier(0);

    // ============== phase 2: compact fg indices ============================
    {
        const unsigned int fl = *(volatile unsigned int*)&g_flags;
        int mode;                     // 0 = int32, 1 = float32, 2 = bool bytes
        if (!(fl & 1u))      mode = 2;
        else if (!(fl & 2u)) mode = 0;
        else if (!(fl & 4u)) mode = 1;
        else                 mode = 2;

        for (int i = tid; i < ((nwords + nthr - 1) / nthr) * nthr; i += nthr) {
            int f0 = 0, f1 = 0, f2 = 0, f3 = 0;
            if (i < nwords) {
                if (mode == 2) {
                    uchar4 v = ((const uchar4*)fg_mask)[i];
                    f0 = v.x != 0; f1 = v.y != 0; f2 = v.z != 0; f3 = v.w != 0;
                } else if (mode == 0) {
                    int4 v = ((const int4*)fg_mask)[i];
                    f0 = v.x != 0; f1 = v.y != 0; f2 = v.z != 0; f3 = v.w != 0;
                } else {
                    float4 v = ((const float4*)fg_mask)[i];
                    f0 = v.x != 0.f; f1 = v.y != 0.f; f2 = v.z != 0.f; f3 = v.w != 0.f;
                }
            }
            int cnt = f0 + f1 + f2 + f3;

            int inc = cnt;
            #pragma unroll
            for (int o = 1; o < 32; o <<= 1) {
                int v = __shfl_up_sync(FULL, inc, o);
                if (lane >= o) inc += v;
            }
            int total = __shfl_sync(FULL, inc, 31);
            int base = 0;
            if (lane == 31 && total) base = atomicAdd(&g_fg_count, total);
            base = __shfl_sync(FULL, base, 31);

            int off = base + inc - cnt;
            int n = i << 2;
            if (f0) g_fg_idx[off++] = n + 0;
            if (f1) g_fg_idx[off++] = n + 1;
            if (f2) g_fg_idx[off++] = n + 2;
            if (f3) g_fg_idx[off++] = n + 3;
        }
    }
    grid_barrier(1);

    // ============== phase 3: process fg anchors ============================
    // 8 lanes per anchor, 4 anchors per warp. Stage each batch into smem via
    // cp.async: per anchor 39 x 16B-ish transfers issued by its 8 lanes in 5
    // rounds (register-free -> all in flight before the wait).
    // Staged layout (floats): [0,80) scores, [80,144) dist, [144,148) tgt box,
    // [148,152) pred box, [152,154) anchor point. Stride 168 floats (672 B).
    __shared__ __align__(16) float stage[NWARPS][4][ANCH_F];

    const int count = *(volatile int*)&g_fg_count;
    const int group = lane >> 3;
    const int gl    = lane & 7;
    const int gw    = blockIdx.x * NWARPS + wid;
    const int nwarp = NBLOCKS * NWARPS;

    double acc_iou = 0.0, acc_dfl = 0.0;

    for (int base_slot = gw * 4; base_slot < count; base_slot += nwarp * 4) {
        __syncwarp();                               // protect stage reuse
        const int  slot   = base_slot + group;
        const bool active = slot < count;
        const int  n      = active ? g_fg_idx[slot] : 0;

        if (active) {
            const char* srow = (const char*)(target_scores + (size_t)n * NC);
            const char* drow = (const char*)(pred_dist + (size_t)n * (4 * RM));
            unsigned int sb = (unsigned int)__cvta_generic_to_shared(
                                  &stage[wid][group][0]);
            #pragma unroll
            for (int r = 0; r < 5; r++) {
                int idx = r * 8 + gl;
                if (idx < 20) {
                    cp16(sb + idx * 16, srow + idx * 16);
                } else if (idx < 36) {
                    cp16(sb + 320 + (idx - 20) * 16, drow + (idx - 20) * 16);
                } else if (idx == 36) {
                    cp16(sb + 576, (const char*)target_bboxes + (size_t)n * 16);
                } else if (idx == 37) {
                    cp16(sb + 592, (const char*)pred_bboxes + (size_t)n * 16);
                } else if (idx == 38) {
                    cp8(sb + 608, (const char*)anchor_points + (size_t)(n % A) * 8);
                }
            }
        }
        cp_wait_all();
        __syncwarp();

        const float* S = &stage[wid][group][0];

        // ---- weight = sum of 80 scores (width-8 reduce) ----
        float4 sq0 = *(const float4*)(S + gl * 4);
        float4 sq1 = *(const float4*)(S + 32 + gl * 4);
        float4 sq2 = (gl < 4) ? *(const float4*)(S + 64 + gl * 4)
                              : make_float4(0, 0, 0, 0);
        float ws = ((sq0.x + sq0.y) + (sq0.z + sq0.w))
                 + ((sq1.x + sq1.y) + (sq1.z + sq1.w))
                 + ((sq2.x + sq2.y) + (sq2.z + sq2.w));
        ws += __shfl_xor_sync(FULL, ws, 1, 8);
        ws += __shfl_xor_sync(FULL, ws, 2, 8);
        ws += __shfl_xor_sync(FULL, ws, 4, 8);

        // ---- base-2 log-softmax over this side's 16 logits ----
        float4 dq0 = *(const float4*)(S + 80 + gl * 8);
        float4 dq1 = *(const float4*)(S + 84 + gl * 8);
        float y[8];
        y[0] = dq0.x * L2E; y[1] = dq0.y * L2E; y[2] = dq0.z * L2E; y[3] = dq0.w * L2E;
        y[4] = dq1.x * L2E; y[5] = dq1.y * L2E; y[6] = dq1.z * L2E; y[7] = dq1.w * L2E;
        float m = y[0];
        #pragma unroll
        for (int k = 1; k < 8; k++) m = fmaxf(m, y[k]);
        m = fmaxf(m, __shfl_xor_sync(FULL, m, 1, 2));
        float se = 0.0f;
        #pragma unroll
        for (int k = 0; k < 8; k++) se += exp2f(y[k] - m);
        se += __shfl_xor_sync(FULL, se, 1, 2);
        float logZ2 = m + log2f(se);

        // ---- target ltrb distance for this side ----
        float4 bt  = *(const float4*)(S + 144);
        float2 apt = *(const float2*)(S + 152);
        const int s = gl >> 1;
        float t = (s == 0) ? (apt.x - bt.x)
                : (s == 1) ? (apt.y - bt.y)
                : (s == 2) ? (bt.z - apt.x)
                :            (bt.w - apt.y);
        t = fminf(fmaxf(t, 0.0f), (float)(RM - 1) - 0.01f);
        const int   tl = (int)t;
        const int   tr = min(tl + 1, RM - 1);
        const float wl = (float)(tl + 1) - t;
        const float wr = 1.0f - wl;

        // pick y at tl/tr (this lane owns bins [bofs, bofs+8))
        const int bofs = (gl & 1) * 8;
        float yl = 0.0f, yr = 0.0f;
        #pragma unroll
        for (int k = 0; k < 8; k++) {
            yl = (tl - bofs == k) ? y[k] : yl;
            yr = (tr - bofs == k) ? y[k] : yr;
        }
        yl += __shfl_xor_sync(FULL, yl, 1, 2);
        yr += __shfl_xor_sync(FULL, yr, 1, 2);

        // dfl (base-2 units) for this side; sum across the 4 side leaders
        float dfl2 = logZ2 - (yl * wl + yr * wr);
        float dc = (((gl & 1) == 0) && active) ? dfl2 : 0.0f;
        dc += __shfl_xor_sync(FULL, dc, 2, 8);
        dc += __shfl_xor_sync(FULL, dc, 4, 8);

        // ---- CIoU on group leader ----
        if (gl == 0 && active) {
            float4 bp = *(const float4*)(S + 148);
            float x11 = bp.x, y11 = bp.y, x21 = bp.z, y21 = bp.w;
            float x12 = bt.x, y12 = bt.y, x22 = bt.z, y22 = bt.w;
            float iw = fmaxf(fminf(x21, x22) - fmaxf(x11, x12), 0.f);
            float ih = fmaxf(fminf(y21, y22) - fmaxf(y11, y12), 0.f);
            float inter = iw * ih;
            float w1 = x21 - x11, h1 = y21 - y11;
            float w2 = x22 - x12, h2 = y22 - y12;
            float uni = w1 * h1 + w2 * h2 - inter + EPSF;
            float iou = __fdividef(inter, uni);
            float cw = fmaxf(x21, x22) - fminf(x11, x12);
            float ch = fmaxf(y21, y22) - fminf(y11, y12);
            float c2 = cw * cw + ch * ch + EPSF;
            float dx = x11 + x21 - x12 - x22;
            float dy = y11 + y21 - y12 - y22;
            float rho2 = (dx * dx + dy * dy) * 0.25f;
            float dat = atanf(__fdividef(w1, h1 + EPSF))
                      - atanf(__fdividef(w2, h2 + EPSF));
            float v = FOUR_OVER_PI2 * dat * dat;
            float alpha = __fdividef(v, 1.0f - iou + v + EPSF);
            float ciou = iou - (__fdividef(rho2, c2) + v * alpha);

            acc_iou += (double)((1.0f - ciou) * ws);
            acc_dfl += (double)dc;              // base-2 units
        }
    }

    // warp reduce (doubles), block reduce, global atomics
    #pragma unroll
    for (int o = 16; o; o >>= 1) {
        acc_iou += __shfl_xor_sync(FULL, acc_iou, o);
        acc_dfl += __shfl_xor_sync(FULL, acc_dfl, o);
    }
    __shared__ double s0[NWARPS], s1[NWARPS];
    if (lane == 0) { s0[wid] = acc_iou; s1[wid] = acc_dfl; }
    __syncthreads();
    if (threadIdx.x == 0) {
        double a0 = 0, a1 = 0;
        #pragma unroll
        for (int i = 0; i < NWARPS; i++) { a0 += s0[i]; a1 += s1[i]; }
        if (a0 != 0.0) atomicAdd(&g_acc[0], a0);
        if (a1 != 0.0) atomicAdd(&g_acc[1], a1);
    }

    grid_barrier(2);

    // ============== finalize (block 0) + self-reset ========================
    if (blockIdx.x == 0 && threadIdx.x == 0) {
        double si  = *(volatile double*)&g_acc[0];
        double sd  = *(volatile double*)&g_acc[1] * (double)LN2;
        double nfg = (double)count;
        double li = si / (double)tss[0];
        double ld = sd / fmax(nfg * 4.0, 1.0);
        if (out_size >= 1) out[0] = (float)li;
        if (out_size >= 2) out[1] = (float)ld;
        g_acc[0] = 0.0; g_acc[1] = 0.0;
        g_flags = 0u; g_fg_count = 0;
    }
}

// ---------------------------------------------------------------------------
// Launch. Inputs (metadata order): pred_dist, pred_bboxes, anchor_points,
// target_bboxes, target_scores, target_scores_sum, fg_mask.
// ---------------------------------------------------------------------------
extern "C" void kernel_launch(void* const* d_in, const int* in_sizes, int n_in,
                              void* d_out, int out_size)
{
    const float* pred_dist     = (const float*)d_in[0];
    const float* pred_bboxes   = (const float*)d_in[1];
    const float* anchor_points = (const float*)d_in[2];
    const float* target_bboxes = (const float*)d_in[3];
    const float* target_scores = (const float*)d_in[4];
    const float* tss           = (const float*)d_in[5];
    const void*  fg_mask       = (const void*)d_in[6];

    const int BA = in_sizes[6];        // B*A anchors
    const int A  = in_sizes[2] / 2;    // anchor_points is (A,2)

    fused_bbox_loss<<<NBLOCKS, NTHREADS>>>(
        pred_dist, pred_bboxes, anchor_points, target_bboxes, target_scores,
        tss, fg_mask, (float*)d_out, BA >> 2, A, out_size);
}

// round 6
// speedup vs baseline: 2.2250x; 1.0875x over previous
#include <cuda_runtime.h>
#include <math.h>

// ---------------------------------------------------------------------------
// BboxLoss (CIoU + DFL), B=32, A=8400, RM=16, NC=80.
// R6: single persistent kernel.
//   phase 1: detect mask dtype        -> grid barrier (release-flag design)
//   phase 2: compact (1 atomic/block) -> grid barrier
//   phase 3: process, ONE pipelined pass per warp (2x4 anchors, cp.async,
//            single wait), block partials, last-block ticket finalize.
// ---------------------------------------------------------------------------

#define EPSF 1e-7f
#define FOUR_OVER_PI2 0.40528473456935108577f   // 4 / pi^2
#define L2E 1.4426950408889634074f              // log2(e)
#define LN2 0.69314718055994530942f             // ln(2)
#define RM 16
#define NC 80

#define NBLOCKS 592
#define NTHREADS 256
#define NWARPS (NTHREADS / 32)
#define ANCH_F 168                               // floats per staged anchor (672B)

__device__ double       g_acc[2];
__device__ unsigned int g_flags;       // bit0=any nonzero, bit1=not-int, bit2=not-float
__device__ int          g_fg_count;
__device__ unsigned int g_ticket;
__device__ int          g_fg_idx[532480];

// Barrier state: arrivals and release flags on separate 128B lines so the
// 591 pollers (read-only) don't contend with arrival RMWs.
struct __align__(128) PadCtr { unsigned int v; unsigned int pad[31]; };
__device__ PadCtr g_arrive[2];
__device__ PadCtr g_release[2];

__device__ __forceinline__ void cp16(unsigned int s, const void* g) {
    asm volatile("cp.async.cg.shared.global [%0], [%1], 16;" :: "r"(s), "l"(g));
}
__device__ __forceinline__ void cp8(unsigned int s, const void* g) {
    asm volatile("cp.async.ca.shared.global [%0], [%1], 8;" :: "r"(s), "l"(g));
}
__device__ __forceinline__ void cp_wait_all() {
    asm volatile("cp.async.wait_all;" ::: "memory");
}

// Monotonic-epoch grid barrier. Pollers spin on a read-only release flag.
__device__ __forceinline__ void grid_barrier(int ph)
{
    __syncthreads();
    if (threadIdx.x == 0) {
        __threadfence();
        unsigned int old   = atomicAdd(&g_arrive[ph].v, 1u);
        unsigned int epoch = old / NBLOCKS + 1u;
        if (old % NBLOCKS == NBLOCKS - 1u) {
            atomicMax(&g_release[ph].v, epoch);     // release everyone
        } else {
            while ((int)(*(volatile unsigned int*)&g_release[ph].v - epoch) < 0)
                __nanosleep(40);
        }
    }
    __syncthreads();
    __threadfence();
}

__global__ __launch_bounds__(NTHREADS, 4)
void fused_bbox_loss(const float* __restrict__ pred_dist,
                     const float* __restrict__ pred_bboxes,
                     const float* __restrict__ anchor_points,
                     const float* __restrict__ target_bboxes,
                     const float* __restrict__ target_scores,
                     const float* __restrict__ tss,
                     const void*  __restrict__ fg_mask,
                     float*       __restrict__ out,
                     int nwords, int A, int out_size)
{
    const int tid   = blockIdx.x * NTHREADS + threadIdx.x;
    const int nthr  = NBLOCKS * NTHREADS;
    const int lane  = threadIdx.x & 31;
    const int wid   = threadIdx.x >> 5;
    const unsigned int FULL = 0xffffffffu;

    __shared__ __align__(16) float stage[NWARPS][8][ANCH_F];
    __shared__ int sh_wsum[NWARPS];
    __shared__ int sh_base;
    __shared__ double s0[NWARPS], s1[NWARPS];

    // ============== phase 1: detect mask dtype =============================
    // Scan min-footprint (BA bytes = nwords u32): in-bounds for every
    // candidate dtype. Bool bytes is the safe fallback.
    {
        unsigned int f = 0u;
        for (int i = tid; i < nwords; i += nthr) {
            unsigned int v = ((const unsigned int*)fg_mask)[i];
            if (v != 0u) f |= 1u;
            if (v > 1u)  f |= 2u;
            float x = __uint_as_float(v);
            if (!(x == 0.0f || x == 1.0f)) f |= 4u;
        }
        #pragma unroll
        for (int o = 16; o; o >>= 1) f |= __shfl_xor_sync(FULL, f, o);
        if (lane == 0 && f) atomicOr(&g_flags, f);
    }
    grid_barrier(0);

    // ============== phase 2: compact (one atomic per block) ================
    {
        const unsigned int fl = *(volatile unsigned int*)&g_flags;
        int mode;                     // 0 = int32, 1 = float32, 2 = bool bytes
        if (!(fl & 1u))      mode = 2;
        else if (!(fl & 2u)) mode = 0;
        else if (!(fl & 4u)) mode = 1;
        else                 mode = 2;

        // here nwords <= nthr (67200 <= 151552): single shot, word i = tid
        const int i = tid;
        int f0 = 0, f1 = 0, f2 = 0, f3 = 0;
        if (i < nwords) {
            if (mode == 2) {
                uchar4 v = ((const uchar4*)fg_mask)[i];
                f0 = v.x != 0; f1 = v.y != 0; f2 = v.z != 0; f3 = v.w != 0;
            } else if (mode == 0) {
                int4 v = ((const int4*)fg_mask)[i];
                f0 = v.x != 0; f1 = v.y != 0; f2 = v.z != 0; f3 = v.w != 0;
            } else {
                float4 v = ((const float4*)fg_mask)[i];
                f0 = v.x != 0.f; f1 = v.y != 0.f; f2 = v.z != 0.f; f3 = v.w != 0.f;
            }
        }
        const int cnt = f0 + f1 + f2 + f3;

        // warp inclusive scan of cnt
        int inc = cnt;
        #pragma unroll
        for (int o = 1; o < 32; o <<= 1) {
            int v = __shfl_up_sync(FULL, inc, o);
            if (lane >= o) inc += v;
        }
        if (lane == 31) sh_wsum[wid] = inc;
        __syncthreads();

        if (threadIdx.x == 0) {
            int run = 0;
            #pragma unroll
            for (int w = 0; w < NWARPS; w++) {
                int t = sh_wsum[w];
                sh_wsum[w] = run;                 // exclusive warp base
                run += t;
            }
            sh_base = run ? atomicAdd(&g_fg_count, run) : 0;
        }
        __syncthreads();

        int off = sh_base + sh_wsum[wid] + inc - cnt;
        int n = i << 2;
        if (f0) g_fg_idx[off++] = n + 0;
        if (f1) g_fg_idx[off++] = n + 1;
        if (f2) g_fg_idx[off++] = n + 2;
        if (f3) g_fg_idx[off++] = n + 3;
    }
    grid_barrier(1);

    // ============== phase 3: process fg anchors ============================
    // 8 lanes per anchor; per pass a warp stages 2 batches x 4 anchors via
    // cp.async (all in flight before one wait), then computes both.
    // Staged layout (floats): [0,80) scores, [80,144) dist, [144,148) tgt
    // box, [148,152) pred box, [152,154) anchor point.
    const int count = *(volatile int*)&g_fg_count;
    const int group = lane >> 3;
    const int gl    = lane & 7;
    const int gw    = blockIdx.x * NWARPS + wid;
    const int nwarp = NBLOCKS * NWARPS;

    double acc_iou = 0.0, acc_dfl = 0.0;

    for (int pass = gw * 8; pass < count; pass += nwarp * 8) {
        __syncwarp();
        // ---- issue both batches ----
        #pragma unroll
        for (int b = 0; b < 2; b++) {
            const int  slot   = pass + b * 4 + group;
            const bool active = slot < count;
            if (!active) continue;
            const int n = g_fg_idx[slot];
            const char* srow = (const char*)(target_scores + (size_t)n * NC);
            const char* drow = (const char*)(pred_dist + (size_t)n * (4 * RM));
            unsigned int sb = (unsigned int)__cvta_generic_to_shared(
                                  &stage[wid][b * 4 + group][0]);
            #pragma unroll
            for (int r = 0; r < 5; r++) {
                int idx = r * 8 + gl;
                if (idx < 20) {
                    cp16(sb + idx * 16, srow + idx * 16);
                } else if (idx < 36) {
                    cp16(sb + 320 + (idx - 20) * 16, drow + (idx - 20) * 16);
                } else if (idx == 36) {
                    cp16(sb + 576, (const char*)target_bboxes + (size_t)n * 16);
                } else if (idx == 37) {
                    cp16(sb + 592, (const char*)pred_bboxes + (size_t)n * 16);
                } else if (idx == 38) {
                    cp8(sb + 608, (const char*)anchor_points + (size_t)(n % A) * 8);
                }
            }
        }
        cp_wait_all();
        __syncwarp();

        // ---- compute both batches ----
        #pragma unroll 1
        for (int b = 0; b < 2; b++) {
            const int  slot   = pass + b * 4 + group;
            const bool active = slot < count;
            const float* S = &stage[wid][b * 4 + group][0];

            // weight = sum of 80 scores (width-8 reduce)
            float4 sq0 = *(const float4*)(S + gl * 4);
            float4 sq1 = *(const float4*)(S + 32 + gl * 4);
            float4 sq2 = (gl < 4) ? *(const float4*)(S + 64 + gl * 4)
                                  : make_float4(0, 0, 0, 0);
            float ws = ((sq0.x + sq0.y) + (sq0.z + sq0.w))
                     + ((sq1.x + sq1.y) + (sq1.z + sq1.w))
                     + ((sq2.x + sq2.y) + (sq2.z + sq2.w));
            ws += __shfl_xor_sync(FULL, ws, 1, 8);
            ws += __shfl_xor_sync(FULL, ws, 2, 8);
            ws += __shfl_xor_sync(FULL, ws, 4, 8);

            // base-2 log-softmax over this side's 16 logits
            float4 dq0 = *(const float4*)(S + 80 + gl * 8);
            float4 dq1 = *(const float4*)(S + 84 + gl * 8);
            float y[8];
            y[0] = dq0.x * L2E; y[1] = dq0.y * L2E;
            y[2] = dq0.z * L2E; y[3] = dq0.w * L2E;
            y[4] = dq1.x * L2E; y[5] = dq1.y * L2E;
            y[6] = dq1.z * L2E; y[7] = dq1.w * L2E;
            float m = y[0];
            #pragma unroll
            for (int k = 1; k < 8; k++) m = fmaxf(m, y[k]);
            m = fmaxf(m, __shfl_xor_sync(FULL, m, 1, 2));
            float se = 0.0f;
            #pragma unroll
            for (int k = 0; k < 8; k++) se += exp2f(y[k] - m);
            se += __shfl_xor_sync(FULL, se, 1, 2);
            float logZ2 = m + log2f(se);

            // target ltrb distance for this side
            float4 bt  = *(const float4*)(S + 144);
            float2 apt = *(const float2*)(S + 152);
            const int s = gl >> 1;
            float t = (s == 0) ? (apt.x - bt.x)
                    : (s == 1) ? (apt.y - bt.y)
                    : (s == 2) ? (bt.z - apt.x)
                    :            (bt.w - apt.y);
            t = fminf(fmaxf(t, 0.0f), (float)(RM - 1) - 0.01f);
            const int   tl = (int)t;
            const int   tr = min(tl + 1, RM - 1);
            const float wl = (float)(tl + 1) - t;
            const float wr = 1.0f - wl;

            const int bofs = (gl & 1) * 8;
            float yl = 0.0f, yr = 0.0f;
            #pragma unroll
            for (int k = 0; k < 8; k++) {
                yl = (tl - bofs == k) ? y[k] : yl;
                yr = (tr - bofs == k) ? y[k] : yr;
            }
            yl += __shfl_xor_sync(FULL, yl, 1, 2);
            yr += __shfl_xor_sync(FULL, yr, 1, 2);

            float dfl2 = logZ2 - (yl * wl + yr * wr);
            float dc = (((gl & 1) == 0) && active) ? dfl2 : 0.0f;
            dc += __shfl_xor_sync(FULL, dc, 2, 8);
            dc += __shfl_xor_sync(FULL, dc, 4, 8);

            if (gl == 0 && active) {
                float4 bp = *(const float4*)(S + 148);
                float x11 = bp.x, y11 = bp.y, x21 = bp.z, y21 = bp.w;
                float x12 = bt.x, y12 = bt.y, x22 = bt.z, y22 = bt.w;
                float iw = fmaxf(fminf(x21, x22) - fmaxf(x11, x12), 0.f);
                float ih = fmaxf(fminf(y21, y22) - fmaxf(y11, y12), 0.f);
                float inter = iw * ih;
                float w1 = x21 - x11, h1 = y21 - y11;
                float w2 = x22 - x12, h2 = y22 - y12;
                float uni = w1 * h1 + w2 * h2 - inter + EPSF;
                float iou = __fdividef(inter, uni);
                float cw = fmaxf(x21, x22) - fminf(x11, x12);
                float ch = fmaxf(y21, y22) - fminf(y11, y12);
                float c2 = cw * cw + ch * ch + EPSF;
                float dx = x11 + x21 - x12 - x22;
                float dy = y11 + y21 - y12 - y22;
                float rho2 = (dx * dx + dy * dy) * 0.25f;
                float dat = atanf(__fdividef(w1, h1 + EPSF))
                          - atanf(__fdividef(w2, h2 + EPSF));
                float v = FOUR_OVER_PI2 * dat * dat;
                float alpha = __fdividef(v, 1.0f - iou + v + EPSF);
                float ciou = iou - (__fdividef(rho2, c2) + v * alpha);

                acc_iou += (double)((1.0f - ciou) * ws);
                acc_dfl += (double)dc;              // base-2 units
            }
        }
    }

    // only lanes 0,8,16,24 hold nonzero partials -> 2 shuffles to lane 0
    acc_iou += __shfl_xor_sync(FULL, acc_iou, 8);
    acc_iou += __shfl_xor_sync(FULL, acc_iou, 16);
    acc_dfl += __shfl_xor_sync(FULL, acc_dfl, 8);
    acc_dfl += __shfl_xor_sync(FULL, acc_dfl, 16);

    if (lane == 0) { s0[wid] = acc_iou; s1[wid] = acc_dfl; }
    __syncthreads();
    if (threadIdx.x == 0) {
        double a0 = 0, a1 = 0;
        #pragma unroll
        for (int i = 0; i < NWARPS; i++) { a0 += s0[i]; a1 += s1[i]; }
        if (a0 != 0.0) atomicAdd(&g_acc[0], a0);
        if (a1 != 0.0) atomicAdd(&g_acc[1], a1);
        __threadfence();
        unsigned int old = atomicAdd(&g_ticket, 1u);   // monotonic ticket
        if (old % NBLOCKS == NBLOCKS - 1u) {
            double si  = *(volatile double*)&g_acc[0];
            double sd  = *(volatile double*)&g_acc[1] * (double)LN2;
            double nfg = (double)count;
            double li = si / (double)tss[0];
            double ld = sd / fmax(nfg * 4.0, 1.0);
            if (out_size >= 1) out[0] = (float)li;
            if (out_size >= 2) out[1] = (float)ld;
            // reset for next replay (all blocks are past these uses)
            g_acc[0] = 0.0; g_acc[1] = 0.0;
            g_flags = 0u; g_fg_count = 0;
        }
    }
}

// ---------------------------------------------------------------------------
// Launch. Inputs (metadata order): pred_dist, pred_bboxes, anchor_points,
// target_bboxes, target_scores, target_scores_sum, fg_mask.
// ---------------------------------------------------------------------------
extern "C" void kernel_launch(void* const* d_in, const int* in_sizes, int n_in,
                              void* d_out, int out_size)
{
    const float* pred_dist     = (const float*)d_in[0];
    const float* pred_bboxes   = (const float*)d_in[1];
    const float* anchor_points = (const float*)d_in[2];
    const float* target_bboxes = (const float*)d_in[3];
    const float* target_scores = (const float*)d_in[4];
    const float* tss           = (const float*)d_in[5];
    const void*  fg_mask       = (const void*)d_in[6];

    const int BA = in_sizes[6];        // B*A anchors
    const int A  = in_sizes[2] / 2;    // anchor_points is (A,2)

    fused_bbox_loss<<<NBLOCKS, NTHREADS>>>(
        pred_dist, pred_bboxes, anchor_points, target_bboxes, target_scores,
        tss, fg_mask, (float*)d_out, BA >> 2, A, out_size);
}